// round 1
// baseline (speedup 1.0000x reference)
#include <cuda_runtime.h>
#include <math.h>

#define TT    1024
#define DD    1024
#define DFFN  1024
#define RR    64
#define GG    8
#define EE    32
#define NEXP  256
#define KK    8
#define FF    (TT*KK)          // 8192 pairs
#define FPAD  (FF + GG*64)     // 8704 (per-group 64-padding headroom)
#define FTILES (FPAD/64)       // 136

// ---------------- scratch (static device globals; no allocation) -----------
__device__ float g_logits[TT*NEXP];
__device__ int   g_sel[TT*KK];
__device__ float g_wtop[TT*KK];
__device__ int   g_counts[GG];
__device__ int   g_off[GG+1];
__device__ int   g_cursor[GG];
__device__ int   g_ptok[FPAD];
__device__ int   g_pe[FPAD];
__device__ float g_pw[FPAD];
__device__ int   g_pslot[FF];
__device__ float g_xg[FPAD*RR];
__device__ float g_xu[FPAD*RR];
__device__ float g_hg[FPAD*RR];
__device__ float g_hu[FPAD*RR];
__device__ float g_act[FPAD*DFFN];   // ~35.6 MB
__device__ float g_xd[FPAD*RR];
__device__ float g_hd[FPAD*RR];
__device__ float g_outf[FPAD*DD];    // ~35.6 MB

// ---------------- init ------------------------------------------------------
__global__ void k_init() {
    if (threadIdx.x < GG) g_counts[threadIdx.x] = 0;
}

// ---------------- router GEMM: logits = x @ Wg  [1024,1024]x[1024,256] ------
__global__ void k_logits(const float* __restrict__ X, const float* __restrict__ W) {
    __shared__ float As[32][65];
    __shared__ float Bs[32][64];
    int tid = threadIdx.x;
    int tx = tid & 15, ty = tid >> 4;
    int m0 = blockIdx.y * 64, n0 = blockIdx.x * 64;
    float acc[16];
#pragma unroll
    for (int i = 0; i < 16; i++) acc[i] = 0.f;

    for (int k0 = 0; k0 < DD; k0 += 32) {
#pragma unroll
        for (int i = 0; i < 8; i++) {
            int idx = tid + i*256;
            int k = idx & 31, m = idx >> 5;
            As[k][m] = X[(m0+m)*DD + k0 + k];
            int n = idx & 63, kb = idx >> 6;
            Bs[kb][n] = W[(k0+kb)*NEXP + n0 + n];
        }
        __syncthreads();
#pragma unroll
        for (int k = 0; k < 32; k++) {
            float a0 = As[k][ty*4+0], a1 = As[k][ty*4+1];
            float a2 = As[k][ty*4+2], a3 = As[k][ty*4+3];
            float4 b = *(const float4*)&Bs[k][tx*4];
            acc[ 0]+=a0*b.x; acc[ 1]+=a0*b.y; acc[ 2]+=a0*b.z; acc[ 3]+=a0*b.w;
            acc[ 4]+=a1*b.x; acc[ 5]+=a1*b.y; acc[ 6]+=a1*b.z; acc[ 7]+=a1*b.w;
            acc[ 8]+=a2*b.x; acc[ 9]+=a2*b.y; acc[10]+=a2*b.z; acc[11]+=a2*b.w;
            acc[12]+=a3*b.x; acc[13]+=a3*b.y; acc[14]+=a3*b.z; acc[15]+=a3*b.w;
        }
        __syncthreads();
    }
#pragma unroll
    for (int i = 0; i < 4; i++) {
        int r = m0 + ty*4 + i;
        float4 o = make_float4(acc[i*4+0], acc[i*4+1], acc[i*4+2], acc[i*4+3]);
        *(float4*)&g_logits[r*NEXP + n0 + tx*4] = o;
    }
}

// ---------------- top-k + softmax + group counts ----------------------------
__global__ void k_topk() {
    int t = blockIdx.x, tid = threadIdx.x;
    __shared__ float sv[256];
    __shared__ int   si[256];
    __shared__ float topv[KK];
    __shared__ int   topi[KK];

    float v = g_logits[t*NEXP + tid];
    for (int k = 0; k < KK; k++) {
        sv[tid] = v; si[tid] = tid;
        __syncthreads();
        for (int s = 128; s > 0; s >>= 1) {
            if (tid < s) {
                float ov = sv[tid+s]; int oi = si[tid+s];
                if (ov > sv[tid] || (ov == sv[tid] && oi < si[tid])) {
                    sv[tid] = ov; si[tid] = oi;
                }
            }
            __syncthreads();
        }
        int mi = si[0];
        if (tid == 0) { topv[k] = sv[0]; topi[k] = mi; }
        __syncthreads();
        if (tid == mi) v = -INFINITY;
    }
    if (tid == 0) {
        float m = topv[0];
        float ex[KK], se = 0.f;
#pragma unroll
        for (int k = 0; k < KK; k++) { ex[k] = expf(topv[k] - m); se += ex[k]; }
        float inv = 1.f / se;
#pragma unroll
        for (int k = 0; k < KK; k++) {
            g_sel[t*KK + k]  = topi[k];
            g_wtop[t*KK + k] = ex[k] * inv;
            atomicAdd(&g_counts[topi[k] / EE], 1);
        }
    }
}

// ---------------- padded group prefix + cursors ------------------------------
__global__ void k_prefix() {
    int o = 0;
    g_off[0] = 0;
    for (int g = 0; g < GG; g++) {
        g_cursor[g] = o;
        o += (g_counts[g] + 63) & ~63;
        g_off[g+1] = o;
    }
}

// ---------------- scatter pairs into group-sorted order ----------------------
__global__ void k_scatter() {
    int idx = blockIdx.x*blockDim.x + threadIdx.x;
    if (idx >= FF) return;
    int e = g_sel[idx];
    int g = e / EE;
    int slot = atomicAdd(&g_cursor[g], 1);
    g_ptok[slot] = idx / KK;
    g_pe[slot]   = e;
    g_pw[slot]   = g_wtop[idx];
    g_pslot[idx] = slot;
}

// ---------------- fill padded slots with harmless dummies ---------------------
__global__ void k_fillpad() {
    int s = blockIdx.x*blockDim.x + threadIdx.x;
    if (s >= g_off[GG]) return;
    int g = 0;
    while (g < GG-1 && s >= g_off[g+1]) g++;
    if (s >= g_off[g] + g_counts[g]) {
        g_ptok[s] = 0;
        g_pe[s]   = g * EE;
        g_pw[s]   = 0.f;
    }
}

// ---------------- grouped gathered GEMM: xin = x[tok] @ uin[g]  (dual) -------
__global__ void k_in(const float* __restrict__ X,
                     const float* __restrict__ Ug,
                     const float* __restrict__ Uu) {
    int row0 = blockIdx.x * 64;
    if (row0 >= g_off[GG]) return;
    int g = 0;
    while (g < GG-1 && row0 >= g_off[g+1]) g++;

    __shared__ int   toks[64];
    __shared__ float As[32][65];
    __shared__ float Bg[32][64];
    __shared__ float Bu[32][64];
    int tid = threadIdx.x;
    if (tid < 64) toks[tid] = g_ptok[row0 + tid];
    __syncthreads();

    const float* Bgp = Ug + (size_t)g*DD*RR;
    const float* Bup = Uu + (size_t)g*DD*RR;
    int tx = tid & 15, ty = tid >> 4;
    float accg[16], accu[16];
#pragma unroll
    for (int i = 0; i < 16; i++) { accg[i] = 0.f; accu[i] = 0.f; }

    for (int k0 = 0; k0 < DD; k0 += 32) {
#pragma unroll
        for (int i = 0; i < 8; i++) {
            int idx = tid + i*256;
            int k = idx & 31, m = idx >> 5;
            As[k][m] = X[toks[m]*DD + k0 + k];
            int n = idx & 63, kb = idx >> 6;
            Bg[kb][n] = Bgp[(k0+kb)*RR + n];
            Bu[kb][n] = Bup[(k0+kb)*RR + n];
        }
        __syncthreads();
#pragma unroll
        for (int k = 0; k < 32; k++) {
            float a[4];
#pragma unroll
            for (int i = 0; i < 4; i++) a[i] = As[k][ty*4+i];
            float4 bg = *(const float4*)&Bg[k][tx*4];
            float4 bu = *(const float4*)&Bu[k][tx*4];
#pragma unroll
            for (int i = 0; i < 4; i++) {
                accg[i*4+0] += a[i]*bg.x; accg[i*4+1] += a[i]*bg.y;
                accg[i*4+2] += a[i]*bg.z; accg[i*4+3] += a[i]*bg.w;
                accu[i*4+0] += a[i]*bu.x; accu[i*4+1] += a[i]*bu.y;
                accu[i*4+2] += a[i]*bu.z; accu[i*4+3] += a[i]*bu.w;
            }
        }
        __syncthreads();
    }
#pragma unroll
    for (int i = 0; i < 4; i++) {
        int r = row0 + ty*4 + i;
        *(float4*)&g_xg[r*RR + tx*4] = make_float4(accg[i*4+0], accg[i*4+1], accg[i*4+2], accg[i*4+3]);
        *(float4*)&g_xu[r*RR + tx*4] = make_float4(accu[i*4+0], accu[i*4+1], accu[i*4+2], accu[i*4+3]);
    }
}

// ---------------- per-pair Tucker core: h = xin @ core[e]  (dual) ------------
__global__ void k_core_gu(const float* __restrict__ Cg, const float* __restrict__ Cu) {
    int p = blockIdx.x;
    if (p >= g_off[GG]) return;
    int tid = threadIdx.x;  // 64
    __shared__ float xg[64], xu[64];
    xg[tid] = g_xg[p*RR + tid];
    xu[tid] = g_xu[p*RR + tid];
    __syncthreads();
    int e = g_pe[p];
    const float* cg = Cg + (size_t)e*RR*RR;
    const float* cu = Cu + (size_t)e*RR*RR;
    float ag = 0.f, au = 0.f;
#pragma unroll 8
    for (int r = 0; r < RR; r++) {
        ag += xg[r] * cg[r*RR + tid];
        au += xu[r] * cu[r*RR + tid];
    }
    g_hg[p*RR + tid] = ag;
    g_hu[p*RR + tid] = au;
}

// ---------------- grouped GEMM (K=64) + SwiGLU: act = silu(hg@Ug)*(hu@Uu) ----
__global__ void k_act(const float* __restrict__ Ug, const float* __restrict__ Uu) {
    int row0 = blockIdx.y * 64;
    if (row0 >= g_off[GG]) return;
    int n0 = blockIdx.x * 64;
    int g = 0;
    while (g < GG-1 && row0 >= g_off[g+1]) g++;

    __shared__ float Ag[32][65], Au[32][65];
    __shared__ float Bg[32][64], Bu[32][64];
    const float* Bgp = Ug + (size_t)g*RR*DFFN;
    const float* Bup = Uu + (size_t)g*RR*DFFN;
    int tid = threadIdx.x;
    int tx = tid & 15, ty = tid >> 4;
    float accg[16], accu[16];
#pragma unroll
    for (int i = 0; i < 16; i++) { accg[i] = 0.f; accu[i] = 0.f; }

    for (int k0 = 0; k0 < RR; k0 += 32) {
#pragma unroll
        for (int i = 0; i < 8; i++) {
            int idx = tid + i*256;
            int k = idx & 31, m = idx >> 5;
            Ag[k][m] = g_hg[(row0+m)*RR + k0 + k];
            Au[k][m] = g_hu[(row0+m)*RR + k0 + k];
            int n = idx & 63, kb = idx >> 6;
            Bg[kb][n] = Bgp[(k0+kb)*DFFN + n0 + n];
            Bu[kb][n] = Bup[(k0+kb)*DFFN + n0 + n];
        }
        __syncthreads();
#pragma unroll
        for (int k = 0; k < 32; k++) {
            float ag[4], au[4];
#pragma unroll
            for (int i = 0; i < 4; i++) { ag[i] = Ag[k][ty*4+i]; au[i] = Au[k][ty*4+i]; }
            float4 bg = *(const float4*)&Bg[k][tx*4];
            float4 bu = *(const float4*)&Bu[k][tx*4];
#pragma unroll
            for (int i = 0; i < 4; i++) {
                accg[i*4+0] += ag[i]*bg.x; accg[i*4+1] += ag[i]*bg.y;
                accg[i*4+2] += ag[i]*bg.z; accg[i*4+3] += ag[i]*bg.w;
                accu[i*4+0] += au[i]*bu.x; accu[i*4+1] += au[i]*bu.y;
                accu[i*4+2] += au[i]*bu.z; accu[i*4+3] += au[i]*bu.w;
            }
        }
        __syncthreads();
    }
#pragma unroll
    for (int i = 0; i < 4; i++) {
        int r = row0 + ty*4 + i;
        float4 o;
        float gv;
        gv  = accg[i*4+0]; o.x = (gv / (1.f + expf(-gv))) * accu[i*4+0];
        gv  = accg[i*4+1]; o.y = (gv / (1.f + expf(-gv))) * accu[i*4+1];
        gv  = accg[i*4+2]; o.z = (gv / (1.f + expf(-gv))) * accu[i*4+2];
        gv  = accg[i*4+3]; o.w = (gv / (1.f + expf(-gv))) * accu[i*4+3];
        *(float4*)&g_act[(size_t)r*DFFN + n0 + tx*4] = o;
    }
}

// ---------------- grouped GEMM: xd = act @ uin_down[g]  [rows,1024]x[1024,64]
__global__ void k_downin(const float* __restrict__ Ud) {
    int row0 = blockIdx.x * 64;
    if (row0 >= g_off[GG]) return;
    int g = 0;
    while (g < GG-1 && row0 >= g_off[g+1]) g++;

    __shared__ float As[32][65];
    __shared__ float Bs[32][64];
    const float* Bp = Ud + (size_t)g*DFFN*RR;
    int tid = threadIdx.x;
    int tx = tid & 15, ty = tid >> 4;
    float acc[16];
#pragma unroll
    for (int i = 0; i < 16; i++) acc[i] = 0.f;

    for (int k0 = 0; k0 < DFFN; k0 += 32) {
#pragma unroll
        for (int i = 0; i < 8; i++) {
            int idx = tid + i*256;
            int k = idx & 31, m = idx >> 5;
            As[k][m] = g_act[(size_t)(row0+m)*DFFN + k0 + k];
            int n = idx & 63, kb = idx >> 6;
            Bs[kb][n] = Bp[(k0+kb)*RR + n];
        }
        __syncthreads();
#pragma unroll
        for (int k = 0; k < 32; k++) {
            float a[4];
#pragma unroll
            for (int i = 0; i < 4; i++) a[i] = As[k][ty*4+i];
            float4 b = *(const float4*)&Bs[k][tx*4];
#pragma unroll
            for (int i = 0; i < 4; i++) {
                acc[i*4+0] += a[i]*b.x; acc[i*4+1] += a[i]*b.y;
                acc[i*4+2] += a[i]*b.z; acc[i*4+3] += a[i]*b.w;
            }
        }
        __syncthreads();
    }
#pragma unroll
    for (int i = 0; i < 4; i++) {
        int r = row0 + ty*4 + i;
        *(float4*)&g_xd[r*RR + tx*4] = make_float4(acc[i*4+0], acc[i*4+1], acc[i*4+2], acc[i*4+3]);
    }
}

// ---------------- per-pair core_down ----------------------------------------
__global__ void k_cored(const float* __restrict__ Cd) {
    int p = blockIdx.x;
    if (p >= g_off[GG]) return;
    int tid = threadIdx.x;  // 64
    __shared__ float xv[64];
    xv[tid] = g_xd[p*RR + tid];
    __syncthreads();
    int e = g_pe[p];
    const float* c = Cd + (size_t)e*RR*RR;
    float a = 0.f;
#pragma unroll 8
    for (int r = 0; r < RR; r++) a += xv[r] * c[r*RR + tid];
    g_hd[p*RR + tid] = a;
}

// ---------------- grouped GEMM (K=64): out_f = (hd @ uout_down[g]) * w -------
__global__ void k_out(const float* __restrict__ Uo) {
    int row0 = blockIdx.y * 64;
    if (row0 >= g_off[GG]) return;
    int n0 = blockIdx.x * 64;
    int g = 0;
    while (g < GG-1 && row0 >= g_off[g+1]) g++;

    __shared__ float As[32][65];
    __shared__ float Bs[32][64];
    __shared__ float pw[64];
    const float* Bp = Uo + (size_t)g*RR*DD;
    int tid = threadIdx.x;
    if (tid < 64) pw[tid] = g_pw[row0 + tid];
    int tx = tid & 15, ty = tid >> 4;
    float acc[16];
#pragma unroll
    for (int i = 0; i < 16; i++) acc[i] = 0.f;

    for (int k0 = 0; k0 < RR; k0 += 32) {
#pragma unroll
        for (int i = 0; i < 8; i++) {
            int idx = tid + i*256;
            int k = idx & 31, m = idx >> 5;
            As[k][m] = g_hd[(row0+m)*RR + k0 + k];
            int n = idx & 63, kb = idx >> 6;
            Bs[kb][n] = Bp[(k0+kb)*DD + n0 + n];
        }
        __syncthreads();
#pragma unroll
        for (int k = 0; k < 32; k++) {
            float a[4];
#pragma unroll
            for (int i = 0; i < 4; i++) a[i] = As[k][ty*4+i];
            float4 b = *(const float4*)&Bs[k][tx*4];
#pragma unroll
            for (int i = 0; i < 4; i++) {
                acc[i*4+0] += a[i]*b.x; acc[i*4+1] += a[i]*b.y;
                acc[i*4+2] += a[i]*b.z; acc[i*4+3] += a[i]*b.w;
            }
        }
        __syncthreads();
    }
#pragma unroll
    for (int i = 0; i < 4; i++) {
        int r = row0 + ty*4 + i;
        float wv = pw[ty*4 + i];
        float4 o = make_float4(acc[i*4+0]*wv, acc[i*4+1]*wv, acc[i*4+2]*wv, acc[i*4+3]*wv);
        *(float4*)&g_outf[(size_t)r*DD + n0 + tx*4] = o;
    }
}

// ---------------- deterministic per-token gather (replaces scatter-add) ------
__global__ void k_gather(float* __restrict__ out) {
    int t = blockIdx.x, tid = threadIdx.x;
    __shared__ int sl[KK];
    if (tid < KK) sl[tid] = g_pslot[t*KK + tid];
    __syncthreads();
#pragma unroll
    for (int d = tid; d < DD; d += 256) {
        float s = 0.f;
#pragma unroll
        for (int k = 0; k < KK; k++) s += g_outf[(size_t)sl[k]*DD + d];
        out[t*DD + d] = s;
    }
}

// ---------------- launch -----------------------------------------------------
extern "C" void kernel_launch(void* const* d_in, const int* in_sizes, int n_in,
                              void* d_out, int out_size) {
    const float* x         = (const float*)d_in[0];
    const float* Wg        = (const float*)d_in[1];
    const float* uin_gate  = (const float*)d_in[2];
    const float* core_gate = (const float*)d_in[3];
    const float* uout_gate = (const float*)d_in[4];
    const float* uin_up    = (const float*)d_in[5];
    const float* core_up   = (const float*)d_in[6];
    const float* uout_up   = (const float*)d_in[7];
    const float* uin_down  = (const float*)d_in[8];
    const float* core_down = (const float*)d_in[9];
    const float* uout_down = (const float*)d_in[10];
    float* out = (float*)d_out;

    k_init   <<<1, 32>>>();
    k_logits <<<dim3(NEXP/64, TT/64), 256>>>(x, Wg);
    k_topk   <<<TT, 256>>>();
    k_prefix <<<1, 1>>>();
    k_scatter<<<FF/256, 256>>>();
    k_fillpad<<<FPAD/256, 256>>>();
    k_in     <<<FTILES, 256>>>(x, uin_gate, uin_up);
    k_core_gu<<<FPAD, 64>>>(core_gate, core_up);
    k_act    <<<dim3(DFFN/64, FTILES), 256>>>(uout_gate, uout_up);
    k_downin <<<FTILES, 256>>>(uin_down);
    k_cored  <<<FPAD, 64>>>(core_down);
    k_out    <<<dim3(DD/64, FTILES), 256>>>(uout_down);
    k_gather <<<TT, 256>>>(out);
}